// round 9
// baseline (speedup 1.0000x reference)
#include <cuda_runtime.h>
#include <cuda_bf16.h>
#include <cstdint>

#define S_LEN  8192
#define BH     32
#define NWIN   511
#define WTOT   (5*128*256 + 128*128)
#define NTH    512

#define M1 (BH*NWIN*8)   // 130816 = 511*256
#define M2 (BH*NWIN*4)   // 65408
#define M3 (BH*NWIN*2)   // 32704
#define M4 (BH*NWIN)     // 16352

__device__ __nv_bfloat16 g_w_hi[WTOT];
__device__ __nv_bfloat16 g_w_lo[WTOT];
__device__ float         g_pew[16 * 128];
__device__ __nv_bfloat16 g_a0_hi[(size_t)BH*NWIN*16*128], g_a0_lo[(size_t)BH*NWIN*16*128];
__device__ __nv_bfloat16 g_a1_hi[(size_t)M1*128],         g_a1_lo[(size_t)M1*128];
__device__ __nv_bfloat16 g_a2_hi[(size_t)M2*128],         g_a2_lo[(size_t)M2*128];
__device__ __nv_bfloat16 g_a3_hi[(size_t)M3*128],         g_a3_lo[(size_t)M3*128];

union U4b { __nv_bfloat16 b[4]; unsigned long long u; };
union U2b { __nv_bfloat16 b[2]; uint32_t u; };

// ---------------------------------------------------------------------------
__global__ void split_weights_kernel(const float* __restrict__ wd,
                                     const float* __restrict__ ws) {
    int i = blockIdx.x * blockDim.x + threadIdx.x;
    if (i >= WTOT) return;
    float v = (i < 5*128*256) ? wd[i] : ws[i - 5*128*256];
    __nv_bfloat16 h = __float2bfloat16(v);
    g_w_hi[i] = h;
    g_w_lo[i] = __float2bfloat16(v - __bfloat162float(h));
}

__global__ void prep_pew_kernel(const float* __restrict__ wd,
                                const float* __restrict__ pe) {
    int idx = blockIdx.x * blockDim.x + threadIdx.x;   // 2048
    int j = idx >> 7, n = idx & 127;
    float s = 0.f;
    for (int d = 0; d < 128; ++d) {
        s += pe[(2*j)*128 + d]   * wd[n*256 + d];
        s += pe[(2*j+1)*128 + d] * wd[n*256 + 128 + d];
    }
    g_pew[idx] = s;
}

__global__ void zero_out_kernel(float* __restrict__ out) {
    int i = blockIdx.x * 256 + threadIdx.x;
    if (i < 4096)
        out[(size_t)(i >> 7) * 512 * 128 + (i & 127)] = 0.f;
}

// ---------------------------------------------------------------------------
__device__ __forceinline__ uint32_t u32p(const void* p) {
    return (uint32_t)__cvta_generic_to_shared(p);
}
__device__ __forceinline__ void ldmx4(uint32_t* r, uint32_t addr) {
    asm volatile("ldmatrix.sync.aligned.m8n8.x4.shared.b16 {%0,%1,%2,%3}, [%4];"
                 : "=r"(r[0]), "=r"(r[1]), "=r"(r[2]), "=r"(r[3]) : "r"(addr));
}
__device__ __forceinline__ void mma16816(float* c, const uint32_t* a,
                                         uint32_t b0, uint32_t b1) {
    asm volatile("mma.sync.aligned.m16n8k16.row.col.f32.bf16.bf16.f32 "
                 "{%0,%1,%2,%3}, {%4,%5,%6,%7}, {%8,%9}, {%0,%1,%2,%3};"
                 : "+f"(c[0]), "+f"(c[1]), "+f"(c[2]), "+f"(c[3])
                 : "r"(a[0]), "r"(a[1]), "r"(a[2]), "r"(a[3]), "r"(b0), "r"(b1));
}
__device__ __forceinline__ float silu_f(float x) { return x / (1.f + __expf(-x)); }

__device__ __forceinline__ void cpasync16(uint32_t dst, const void* src) {
    asm volatile("cp.async.cg.shared.global [%0], [%1], 16;" :: "r"(dst), "l"(src));
}
__device__ __forceinline__ void cpasync16z(uint32_t dst, const void* src, bool v) {
    int sz = v ? 16 : 0;
    asm volatile("cp.async.cg.shared.global [%0], [%1], 16, %2;"
                 :: "r"(dst), "l"(src), "r"(sz));
}
__device__ __forceinline__ void cpcommit() {
    asm volatile("cp.async.commit_group;" ::: "memory");
}
__device__ __forceinline__ void cpwait0() { asm volatile("cp.async.wait_group 0;" ::: "memory"); }

__device__ __forceinline__ void silu_split_store(__nv_bfloat16* hiA, __nv_bfloat16* loA,
                                                 size_t idx, float v0, float v1) {
    v0 = silu_f(v0); v1 = silu_f(v1);
    U2b hi, lo;
    hi.b[0] = __float2bfloat16(v0);
    hi.b[1] = __float2bfloat16(v1);
    lo.b[0] = __float2bfloat16(v0 - __bfloat162float(hi.b[0]));
    lo.b[1] = __float2bfloat16(v1 - __bfloat162float(hi.b[1]));
    *(uint32_t*)(hiA + idx) = hi.u;
    *(uint32_t*)(loA + idx) = lo.u;
}

// ---------------------------------------------------------------------------
// kstep-16 MMA over [kq0,kq1) of a 64-col chunk. Warp tile R row-tiles x 4
// n-tiles. B ldmatrix.x4 fetches TWO n-tiles per kstep (ratio 1.0 at R=4).
// ---------------------------------------------------------------------------
template<int R>
__device__ __forceinline__ void mma_chunk_ks(
    float (&acc)[R][4][4],
    uint32_t aHiU, uint32_t aLoU, uint32_t bHiU, uint32_t bLoU,
    int rBeg, int cg, int lane, int kq0, int kq1)
{
    const int a_rowoff = (lane & 7) + (((lane >> 3) & 1) << 3);
    const int a_koff   = (lane >> 4) << 3;
    const int b_nl     = lane & 7;
    const int b_koff   = ((lane >> 3) & 1) << 3;
    const int b_nts    = lane >> 4;
#pragma unroll
    for (int kq = kq0; kq < kq1; kq += 16) {
        uint32_t aH[R][4], aL[R][4];
#pragma unroll
        for (int i = 0; i < R; i++) {
            int Rr = (rBeg + i) * 16 + a_rowoff;
            int kc = kq + a_koff;
            int offs = Rr * 128 + (((kc >> 3) ^ (Rr & 7)) << 4);
            ldmx4(aH[i], aHiU + offs);
            ldmx4(aL[i], aLoU + offs);
        }
#pragma unroll
        for (int tp = 0; tp < 2; tp++) {
            int n = (cg * 4 + tp * 2 + b_nts) * 8 + b_nl;
            int kc = kq + b_koff;
            int cs = (kc >> 3) ^ (n & 7);
            uint32_t boff = (uint32_t)(n * 128 + (cs << 4));
            uint32_t bH[4], bL[4];
            ldmx4(bH, bHiU + boff);
            ldmx4(bL, bLoU + boff);
#pragma unroll
            for (int sub = 0; sub < 2; sub++) {
                int t = tp * 2 + sub;
#pragma unroll
                for (int i = 0; i < R; i++) {
                    float* cc = acc[i][t];
                    mma16816(cc, aH[i], bH[2*sub], bH[2*sub+1]);
                    mma16816(cc, aL[i], bH[2*sub], bH[2*sub+1]);
                    mma16816(cc, aH[i], bL[2*sub], bL[2*sub+1]);
                }
            }
        }
    }
}

// B chunk [128 n x 64 k] hi+lo -> SW-style smem
__device__ __forceinline__ void gs_prefB(uint32_t bufU,
        const __nv_bfloat16* __restrict__ wh, const __nv_bfloat16* __restrict__ wl,
        int KDIM, int kb, int tid) {
#pragma unroll
    for (int it = 0; it < 4; ++it) {
        int i = tid + it * NTH;                  // 2048
        int g = i & 7, n = (i >> 3) & 127, hl = i >> 10;
        const __nv_bfloat16* src = (hl ? wl : wh) + n * KDIM + kb + g * 8;
        uint32_t dst = bufU + hl * 16384 + n * 128 + ((g ^ (n & 7)) << 4);
        cpasync16(dst, src);
    }
}

// A chunk [TILE rows x 64 k] hi+lo from pre-split act arrays (KDIM=256)
template<int TILE>
__device__ __forceinline__ void gs_prefA(uint32_t bufU,
        const __nv_bfloat16* __restrict__ aHi, const __nv_bfloat16* __restrict__ aLo,
        int Mtot, int mt, int kb, int tid) {
#pragma unroll
    for (int it = 0; it < TILE/32; ++it) {
        int i = tid + it * NTH;                  // TILE*16 copies
        int g = i & 7, row = (i >> 3) & (TILE - 1), hl = (i >> 3) / TILE;
        int mrow = mt * TILE + row;
        bool v = mrow < Mtot;
        const __nv_bfloat16* src = (hl ? aLo : aHi)
                                 + (size_t)(v ? mrow : 0) * 256 + kb + g * 8;
        uint32_t dst = bufU + hl * (TILE * 128) + row * 128 + ((g ^ (row & 7)) << 4);
        cpasync16z(dst, src, v);
    }
}

// ===========================================================================
// G0: TILE=256 pairs, R=4. A staged fp32->split via LDG/STS in half-chunks
// interleaved with the two MMA halves (held regs: 16).
// smem: A bufs @0,65536 (hi+0, lo+32768); B bufs @131072,163840; pew @196608
// ===========================================================================
#define G0_ABUF   65536
#define G0_OFFB(b) (131072 + (b)*32768)
#define G0_PEW    196608
#define G0_SMEM   (196608 + 8192)

__device__ __forceinline__ void g0_ldg_half(float4* rA, const float* __restrict__ Abase,
                                            int ch, int tid, int h) {
#pragma unroll
    for (int t = 0; t < 4; ++t) {
        int f = tid + (h * 4 + t) * NTH;      // 0..4095
        int row = f >> 4, fc = f & 15;
        rA[t] = *(const float4*)(Abase + (size_t)row * 256 + ch * 64 + 4 * fc);
    }
}
__device__ __forceinline__ void g0_sts_half(char* sm, int bufByte, const float4* rA,
                                            int tid, int h) {
#pragma unroll
    for (int t = 0; t < 4; ++t) {
        int f = tid + (h * 4 + t) * NTH;
        int row = f >> 4, fc = f & 15;
        float v[4] = {rA[t].x, rA[t].y, rA[t].z, rA[t].w};
        U4b hi, lo;
#pragma unroll
        for (int j = 0; j < 4; j++) {
            hi.b[j] = __float2bfloat16(v[j]);
            lo.b[j] = __float2bfloat16(v[j] - __bfloat162float(hi.b[j]));
        }
        int g = fc >> 1;
        int off = bufByte + row * 128 + ((g ^ (row & 7)) << 4) + (fc & 1) * 8;
        *(unsigned long long*)(sm + off)         = hi.u;
        *(unsigned long long*)(sm + off + 32768) = lo.u;
    }
}

__global__ void __launch_bounds__(NTH, 1)
g0_kernel(const float* __restrict__ k)
{
    extern __shared__ char sm[];
    const uint32_t sb = u32p(sm);
    float* pews = (float*)(sm + G0_PEW);
    const int mt = blockIdx.x, bh = blockIdx.y;
    const int tid = threadIdx.x, lane = tid & 31, wid = tid >> 5;
    const int rBeg = (wid & 3) * 4;
    const int cg   = wid >> 2;
    const float* Abase = k + (size_t)bh * S_LEN * 128 + (size_t)mt * 256 * 256;

    float acc[4][4][4];
#pragma unroll
    for (int i = 0; i < 4; i++)
#pragma unroll
        for (int t = 0; t < 4; t++)
#pragma unroll
            for (int j = 0; j < 4; j++) acc[i][t][j] = 0.f;

    ((float4*)pews)[tid] = ((const float4*)g_pew)[tid];

    // prologue: B0 + A0
    gs_prefB(sb + G0_OFFB(0), g_w_hi, g_w_lo, 256, 0, tid);
    cpcommit();
    {
        float4 rA[4];
        g0_ldg_half(rA, Abase, 0, tid, 0);
        g0_sts_half(sm, 0, rA, tid, 0);
        g0_ldg_half(rA, Abase, 0, tid, 1);
        g0_sts_half(sm, 0, rA, tid, 1);
    }
    cpwait0();
    __syncthreads();

    for (int c = 0; c < 4; ++c) {
        float4 rA[4];
        if (c < 3) {
            gs_prefB(sb + G0_OFFB((c + 1) & 1), g_w_hi, g_w_lo, 256, (c + 1) * 64, tid);
            cpcommit();
            g0_ldg_half(rA, Abase, c + 1, tid, 0);
        }
        const uint32_t aU = sb + (c & 1) * G0_ABUF;
        const uint32_t bU = sb + G0_OFFB(c & 1);
        mma_chunk_ks<4>(acc, aU, aU + 32768, bU, bU + 16384, rBeg, cg, lane, 0, 32);
        if (c < 3) {
            g0_sts_half(sm, ((c + 1) & 1) * G0_ABUF, rA, tid, 0);
            g0_ldg_half(rA, Abase, c + 1, tid, 1);
        }
        mma_chunk_ks<4>(acc, aU, aU + 32768, bU, bU + 16384, rBeg, cg, lane, 32, 64);
        if (c < 3) {
            g0_sts_half(sm, ((c + 1) & 1) * G0_ABUF, rA, tid, 1);
            cpwait0();
        }
        __syncthreads();
    }

    // epilogue: pair j feeds two act0 rows (different pe bias)
    const int r0 = lane >> 2, cof = (lane & 3) << 1;
    const size_t bhbase = (size_t)bh * NWIN;
#pragma unroll
    for (int i = 0; i < 4; i++)
#pragma unroll
        for (int t = 0; t < 4; t++) {
            int col = (cg * 4 + t) * 8 + cof;
            float* cc = acc[i][t];
#pragma unroll
            for (int h = 0; h < 2; h++) {
                int r = (rBeg + i) * 16 + r0 + (h << 3);
                int j = mt * 256 + r;
                float y0 = cc[2*h], y1 = cc[2*h + 1];
                int w1 = j >> 3, ra = j & 7;
                if (w1 < NWIN) {
                    float2 bb = *(const float2*)(pews + ra * 128 + col);
                    silu_split_store(g_a0_hi, g_a0_lo,
                        ((bhbase + w1) * 16 + ra) * 128 + col, y0 + bb.x, y1 + bb.y);
                }
                if (w1 >= 1) {
                    int rb = ra + 8;
                    float2 bb = *(const float2*)(pews + rb * 128 + col);
                    silu_split_store(g_a0_hi, g_a0_lo,
                        ((bhbase + (w1 - 1)) * 16 + rb) * 128 + col, y0 + bb.x, y1 + bb.y);
                }
            }
        }
}

// ===========================================================================
// G1..G3
// ===========================================================================
template<int STAGE, int TILE>
__global__ void __launch_bounds__(NTH, 1)
gstage_kernel()
{
    constexpr int R    = TILE / 64;
    constexpr int ABUF = TILE * 256;
    constexpr int ALO  = TILE * 128;
    const __nv_bfloat16 *aHi, *aLo, *wh, *wl;
    __nv_bfloat16 *oHi, *oLo;
    int Mtot;
    if constexpr (STAGE == 1) { aHi=g_a0_hi; aLo=g_a0_lo; wh=g_w_hi+32768; wl=g_w_lo+32768; oHi=g_a1_hi; oLo=g_a1_lo; Mtot=M1; }
    if constexpr (STAGE == 2) { aHi=g_a1_hi; aLo=g_a1_lo; wh=g_w_hi+65536; wl=g_w_lo+65536; oHi=g_a2_hi; oLo=g_a2_lo; Mtot=M2; }
    if constexpr (STAGE == 3) { aHi=g_a2_hi; aLo=g_a2_lo; wh=g_w_hi+98304; wl=g_w_lo+98304; oHi=g_a3_hi; oLo=g_a3_lo; Mtot=M3; }

    extern __shared__ char sm[];
    const uint32_t sb = u32p(sm);
    const int mt = blockIdx.x;
    const int tid = threadIdx.x, lane = tid & 31, wid = tid >> 5;
    const int rBeg = (wid & 3) * R;
    const int cg   = wid >> 2;

    float acc[R][4][4];
#pragma unroll
    for (int i = 0; i < R; i++)
#pragma unroll
        for (int t = 0; t < 4; t++)
#pragma unroll
            for (int j = 0; j < 4; j++) acc[i][t][j] = 0.f;

    gs_prefA<TILE>(sb, aHi, aLo, Mtot, mt, 0, tid);
    gs_prefB(sb + 2 * ABUF, wh, wl, 256, 0, tid);
    cpcommit();

    for (int c = 0; c < 4; ++c) {
        cpwait0();
        __syncthreads();
        if (c < 3) {
            int b = (c + 1) & 1;
            gs_prefA<TILE>(sb + b * ABUF, aHi, aLo, Mtot, mt, (c + 1) * 64, tid);
            gs_prefB(sb + 2 * ABUF + b * 32768, wh, wl, 256, (c + 1) * 64, tid);
            cpcommit();
        }
        const uint32_t aU = sb + (c & 1) * ABUF;
        const uint32_t bU = sb + 2 * ABUF + (c & 1) * 32768;
        mma_chunk_ks<R>(acc, aU, aU + ALO, bU, bU + 16384, rBeg, cg, lane, 0, 64);
    }

    const int r0 = lane >> 2, cof = (lane & 3) << 1;
#pragma unroll
    for (int i = 0; i < R; i++)
#pragma unroll
        for (int t = 0; t < 4; t++) {
            int col = (cg * 4 + t) * 8 + cof;
            float* cc = acc[i][t];
#pragma unroll
            for (int h = 0; h < 2; h++) {
                int r = (rBeg + i) * 16 + r0 + (h << 3);
                int m = mt * TILE + r;
                if (m < Mtot)
                    silu_split_store(oHi, oLo, (size_t)m * 128 + col,
                                     cc[2*h], cc[2*h + 1]);
            }
        }
}

// ===========================================================================
// G45: stage 4 (GEMM K=256 from a3) then stage 5 (K=128) from smem, fused.
// TILE=128, R=2. smem: A bufs @0,32768; B bufs @65536,98304.
// ===========================================================================
__global__ void __launch_bounds__(NTH, 1)
g45_kernel(float* __restrict__ gout)
{
    constexpr int ABUF = 32768, ALO = 16384;
    extern __shared__ char sm[];
    const uint32_t sb = u32p(sm);
    const int mt = blockIdx.x;
    const int tid = threadIdx.x, lane = tid & 31, wid = tid >> 5;
    const int rBeg = (wid & 3) * 2;
    const int cg   = wid >> 2;
    const int r0 = lane >> 2, cof = (lane & 3) << 1;

    float acc[2][4][4];
#pragma unroll
    for (int i = 0; i < 2; i++)
#pragma unroll
        for (int t = 0; t < 4; t++)
#pragma unroll
            for (int j = 0; j < 4; j++) acc[i][t][j] = 0.f;

    // ---- stage 4 mainloop ----
    gs_prefA<128>(sb, g_a3_hi, g_a3_lo, M4, mt, 0, tid);
    gs_prefB(sb + 2 * ABUF, g_w_hi + 131072, g_w_lo + 131072, 256, 0, tid);
    cpcommit();
    for (int c = 0; c < 4; ++c) {
        cpwait0();
        __syncthreads();
        if (c < 3) {
            int b = (c + 1) & 1;
            gs_prefA<128>(sb + b * ABUF, g_a3_hi, g_a3_lo, M4, mt, (c + 1) * 64, tid);
            gs_prefB(sb + 2 * ABUF + b * 32768, g_w_hi + 131072, g_w_lo + 131072,
                     256, (c + 1) * 64, tid);
            cpcommit();
        }
        const uint32_t aU = sb + (c & 1) * ABUF;
        const uint32_t bU = sb + 2 * ABUF + (c & 1) * 32768;
        mma_chunk_ks<2>(acc, aU, aU + ALO, bU, bU + 16384, rBeg, cg, lane, 0, 64);
    }
    __syncthreads();   // all reads of stage-4 buffers done

    // ---- stage-5 staging: B (w_stop) via cp.async, A = silu(stage4) via STS
    gs_prefB(sb + 2 * ABUF,         g_w_hi + 163840, g_w_lo + 163840, 128, 0, tid);
    gs_prefB(sb + 2 * ABUF + 32768, g_w_hi + 163840, g_w_lo + 163840, 128, 64, tid);
    cpcommit();
#pragma unroll
    for (int i = 0; i < 2; i++)
#pragma unroll
        for (int t = 0; t < 4; t++) {
            int col = (cg * 4 + t) * 8 + cof;
            float* cc = acc[i][t];
#pragma unroll
            for (int h = 0; h < 2; h++) {
                int r = (rBeg + i) * 16 + r0 + (h << 3);
                float v0 = silu_f(cc[2*h]), v1 = silu_f(cc[2*h + 1]);
                U2b hi, lo;
                hi.b[0] = __float2bfloat16(v0);
                hi.b[1] = __float2bfloat16(v1);
                lo.b[0] = __float2bfloat16(v0 - __bfloat162float(hi.b[0]));
                lo.b[1] = __float2bfloat16(v1 - __bfloat162float(hi.b[1]));
                int b = col >> 6, lc = col & 63, g = lc >> 3;
                int off = b * ABUF + r * 128 + ((g ^ (r & 7)) << 4) + (lc & 7) * 2;
                *(uint32_t*)(sm + off)       = hi.u;
                *(uint32_t*)(sm + off + ALO) = lo.u;
            }
        }
    cpwait0();
    __syncthreads();

    // ---- stage 5: 2 resident chunks ----
    float acc5[2][4][4];
#pragma unroll
    for (int i = 0; i < 2; i++)
#pragma unroll
        for (int t = 0; t < 4; t++)
#pragma unroll
            for (int j = 0; j < 4; j++) acc5[i][t][j] = 0.f;
#pragma unroll
    for (int c = 0; c < 2; ++c) {
        const uint32_t aU = sb + c * ABUF;
        const uint32_t bU = sb + 2 * ABUF + c * 32768;
        mma_chunk_ks<2>(acc5, aU, aU + ALO, bU, bU + 16384, rBeg, cg, lane, 0, 64);
    }

    // ---- final epilogue -> gmem ----
#pragma unroll
    for (int i = 0; i < 2; i++)
#pragma unroll
        for (int t = 0; t < 4; t++) {
            int col = (cg * 4 + t) * 8 + cof;
            float* cc = acc5[i][t];
#pragma unroll
            for (int h = 0; h < 2; h++) {
                int r = (rBeg + i) * 16 + r0 + (h << 3);
                int m = mt * 128 + r;
                if (m < M4) {
                    int bh = m / NWIN, w = m % NWIN;
                    *(float2*)(gout + ((size_t)bh * 512 + 1 + w) * 128 + col) =
                        make_float2(cc[2*h], cc[2*h + 1]);
                }
            }
        }
}

extern "C" void kernel_launch(void* const* d_in, const int* in_sizes, int n_in,
                              void* d_out, int out_size)
{
    const float* k  = (const float*)d_in[0];
    const float* pe = (const float*)d_in[1];
    const float* wd = (const float*)d_in[2];
    const float* ws = (const float*)d_in[3];
    float* out = (float*)d_out;

    split_weights_kernel<<<(WTOT + 255) / 256, 256>>>(wd, ws);
    prep_pew_kernel<<<8, 256>>>(wd, pe);
    zero_out_kernel<<<16, 256>>>(out);

    cudaFuncSetAttribute(g0_kernel,
                         cudaFuncAttributeMaxDynamicSharedMemorySize, G0_SMEM);
    cudaFuncSetAttribute(gstage_kernel<1, 256>,
                         cudaFuncAttributeMaxDynamicSharedMemorySize, 196608);
    cudaFuncSetAttribute(gstage_kernel<2, 256>,
                         cudaFuncAttributeMaxDynamicSharedMemorySize, 196608);
    cudaFuncSetAttribute(gstage_kernel<3, 128>,
                         cudaFuncAttributeMaxDynamicSharedMemorySize, 131072);
    cudaFuncSetAttribute(g45_kernel,
                         cudaFuncAttributeMaxDynamicSharedMemorySize, 131072);

    g0_kernel<<<dim3(16, BH), NTH, G0_SMEM>>>(k);
    gstage_kernel<1, 256><<<M1 / 256,          NTH, 196608>>>();   // 511
    gstage_kernel<2, 256><<<(M2 + 255) / 256,  NTH, 196608>>>();   // 256
    gstage_kernel<3, 128><<<(M3 + 127) / 128,  NTH, 131072>>>();   // 256
    g45_kernel<<<(M4 + 127) / 128, NTH, 131072>>>(out);            // 128
}

// round 10
// speedup vs baseline: 1.1320x; 1.1320x over previous
#include <cuda_runtime.h>
#include <cuda_bf16.h>
#include <cstdint>

#define S_LEN  8192
#define BH     32
#define NWIN   511
#define WTOT   (5*128*256 + 128*128)

#define M1 (BH*NWIN*8)   // 130816
#define M2 (BH*NWIN*4)   // 65408
#define M3 (BH*NWIN*2)   // 32704
#define M4 (BH*NWIN)     // 16352

__device__ __nv_bfloat16 g_w_hi[WTOT];
__device__ __nv_bfloat16 g_w_lo[WTOT];
__device__ float         g_pew[16 * 128];
__device__ __nv_bfloat16 g_a0_hi[(size_t)BH*NWIN*16*128], g_a0_lo[(size_t)BH*NWIN*16*128];
__device__ __nv_bfloat16 g_a1_hi[(size_t)M1*128],         g_a1_lo[(size_t)M1*128];
__device__ __nv_bfloat16 g_a2_hi[(size_t)M2*128],         g_a2_lo[(size_t)M2*128];
__device__ __nv_bfloat16 g_a3_hi[(size_t)M3*128],         g_a3_lo[(size_t)M3*128];
__device__ __nv_bfloat16 g_a4_hi[(size_t)M4*128],         g_a4_lo[(size_t)M4*128];

union U4b { __nv_bfloat16 b[4]; unsigned long long u; };
union U2b { __nv_bfloat16 b[2]; uint32_t u; };

// ---------------------------------------------------------------------------
__global__ void split_weights_kernel(const float* __restrict__ wd,
                                     const float* __restrict__ ws) {
    int i = blockIdx.x * blockDim.x + threadIdx.x;
    if (i >= WTOT) return;
    float v = (i < 5*128*256) ? wd[i] : ws[i - 5*128*256];
    __nv_bfloat16 h = __float2bfloat16(v);
    g_w_hi[i] = h;
    g_w_lo[i] = __float2bfloat16(v - __bfloat162float(h));
}

__global__ void prep_pew_kernel(const float* __restrict__ wd,
                                const float* __restrict__ pe) {
    int idx = blockIdx.x * blockDim.x + threadIdx.x;   // 2048
    int j = idx >> 7, n = idx & 127;
    float s = 0.f;
    for (int d = 0; d < 128; ++d) {
        s += pe[(2*j)*128 + d]   * wd[n*256 + d];
        s += pe[(2*j+1)*128 + d] * wd[n*256 + 128 + d];
    }
    g_pew[idx] = s;
}

__global__ void zero_out_kernel(float* __restrict__ out) {
    int i = blockIdx.x * 256 + threadIdx.x;
    if (i < 4096)
        out[(size_t)(i >> 7) * 512 * 128 + (i & 127)] = 0.f;
}

// ---------------------------------------------------------------------------
__device__ __forceinline__ uint32_t u32p(const void* p) {
    return (uint32_t)__cvta_generic_to_shared(p);
}
__device__ __forceinline__ void ldmx4(uint32_t* r, uint32_t addr) {
    asm volatile("ldmatrix.sync.aligned.m8n8.x4.shared.b16 {%0,%1,%2,%3}, [%4];"
                 : "=r"(r[0]), "=r"(r[1]), "=r"(r[2]), "=r"(r[3]) : "r"(addr));
}
__device__ __forceinline__ void mma16816(float* c, const uint32_t* a,
                                         uint32_t b0, uint32_t b1) {
    asm volatile("mma.sync.aligned.m16n8k16.row.col.f32.bf16.bf16.f32 "
                 "{%0,%1,%2,%3}, {%4,%5,%6,%7}, {%8,%9}, {%0,%1,%2,%3};"
                 : "+f"(c[0]), "+f"(c[1]), "+f"(c[2]), "+f"(c[3])
                 : "r"(a[0]), "r"(a[1]), "r"(a[2]), "r"(a[3]), "r"(b0), "r"(b1));
}
__device__ __forceinline__ float silu_f(float x) { return x / (1.f + __expf(-x)); }

__device__ __forceinline__ void cpasync16(uint32_t dst, const void* src) {
    asm volatile("cp.async.cg.shared.global [%0], [%1], 16;" :: "r"(dst), "l"(src));
}
__device__ __forceinline__ void cpasync16z(uint32_t dst, const void* src, bool v) {
    int sz = v ? 16 : 0;
    asm volatile("cp.async.cg.shared.global [%0], [%1], 16, %2;"
                 :: "r"(dst), "l"(src), "r"(sz));
}
__device__ __forceinline__ void cpcommit() {
    asm volatile("cp.async.commit_group;" ::: "memory");
}
__device__ __forceinline__ void cpwait0() { asm volatile("cp.async.wait_group 0;" ::: "memory"); }

__device__ __forceinline__ void silu_split_store(__nv_bfloat16* hiA, __nv_bfloat16* loA,
                                                 size_t idx, float v0, float v1) {
    v0 = silu_f(v0); v1 = silu_f(v1);
    U2b hi, lo;
    hi.b[0] = __float2bfloat16(v0);
    hi.b[1] = __float2bfloat16(v1);
    lo.b[0] = __float2bfloat16(v0 - __bfloat162float(hi.b[0]));
    lo.b[1] = __float2bfloat16(v1 - __bfloat162float(hi.b[1]));
    *(uint32_t*)(hiA + idx) = hi.u;
    *(uint32_t*)(loA + idx) = lo.u;
}

// B chunk [128 n x 64 k] hi+lo -> swizzled smem (NT = threads in CTA)
template<int NT>
__device__ __forceinline__ void prefB(uint32_t bufU,
        const __nv_bfloat16* __restrict__ wh, const __nv_bfloat16* __restrict__ wl,
        int KDIM, int kb, int tid) {
#pragma unroll
    for (int it = 0; it < 2048 / NT; ++it) {
        int i = tid + it * NT;
        int g = i & 7, n = (i >> 3) & 127, hl = i >> 10;
        const __nv_bfloat16* src = (hl ? wl : wh) + n * KDIM + kb + g * 8;
        uint32_t dst = bufU + hl * 16384 + n * 128 + ((g ^ (n & 7)) << 4);
        cpasync16(dst, src);
    }
}

// ===========================================================================
// r7 proven G0: TILE=128 pairs, 512 threads, R=2/T=4, LDG/split/STS inline.
// smem: A bufs @0,32768 (hi+0, lo+16384); B @65536,98304; pew @131072
// ===========================================================================
template<int R>
__device__ __forceinline__ void mma_chunk64(
    float (&acc)[R][4][4],
    uint32_t aHiU, uint32_t aLoU, uint32_t bHiU, uint32_t bLoU,
    int rBeg, int ntBeg, int lane)
{
    const int a_mat    = lane >> 3;
    const int a_rowoff = (lane & 7) + ((a_mat & 1) << 3);
    const int a_koff   = (a_mat >> 1) << 3;
    const int b_nl     = lane & 7;
    const int b_km     = (lane >> 3) << 3;
#pragma unroll
    for (int kq = 0; kq < 64; kq += 32) {
        uint32_t aH[R][8], aL[R][8];
#pragma unroll
        for (int i = 0; i < R; i++) {
            int Rr = (rBeg + i) * 16 + a_rowoff;
            int kc0 = kq + a_koff;
            int offs0 = Rr * 128 + (((kc0 >> 3) ^ (Rr & 7)) << 4);
            int offs1 = Rr * 128 + ((((kc0 + 16) >> 3) ^ (Rr & 7)) << 4);
            ldmx4(aH[i], aHiU + offs0);
            ldmx4(aH[i] + 4, aHiU + offs1);
            ldmx4(aL[i], aLoU + offs0);
            ldmx4(aL[i] + 4, aLoU + offs1);
        }
#pragma unroll
        for (int t = 0; t < 4; t++) {
            int n = ((ntBeg + t) << 3) + b_nl;
            int cs = ((kq + b_km) >> 3) ^ (n & 7);
            uint32_t boff = n * 128 + (cs << 4);
            uint32_t bH[4], bL[4];
            ldmx4(bH, bHiU + boff);
            ldmx4(bL, bLoU + boff);
#pragma unroll
            for (int i = 0; i < R; i++) {
                float* cc = acc[i][t];
                mma16816(cc, aH[i], bH[0], bH[1]);
                mma16816(cc, aL[i], bH[0], bH[1]);
                mma16816(cc, aH[i], bL[0], bL[1]);
                mma16816(cc, aH[i] + 4, bH[2], bH[3]);
                mma16816(cc, aL[i] + 4, bH[2], bH[3]);
                mma16816(cc, aH[i] + 4, bL[2], bL[3]);
            }
        }
    }
}

#define G0_OFFB(b) (65536 + (b)*32768)
#define G0_PEW     131072
#define G0_SMEM    (131072 + 8192)

__device__ __forceinline__ void g0_ldsts_A(char* sm, int bufByte,
        const float* __restrict__ Abase, int ch, int tid) {
#pragma unroll
    for (int t = 0; t < 4; ++t) {
        int f = tid + t * 512, row = f >> 4, fc = f & 15;
        float4 v4 = *(const float4*)(Abase + (size_t)row * 256 + ch * 64 + 4 * fc);
        float v[4] = {v4.x, v4.y, v4.z, v4.w};
        U4b hi, lo;
#pragma unroll
        for (int j = 0; j < 4; j++) {
            hi.b[j] = __float2bfloat16(v[j]);
            lo.b[j] = __float2bfloat16(v[j] - __bfloat162float(hi.b[j]));
        }
        int g = fc >> 1;
        int off = bufByte + row * 128 + ((g ^ (row & 7)) << 4) + (fc & 1) * 8;
        *(unsigned long long*)(sm + off)         = hi.u;
        *(unsigned long long*)(sm + off + 16384) = lo.u;
    }
}

__global__ void __launch_bounds__(512, 1)
g0_kernel(const float* __restrict__ k)
{
    extern __shared__ char sm[];
    const uint32_t sb = u32p(sm);
    float* pews = (float*)(sm + G0_PEW);
    const int mt = blockIdx.x, bh = blockIdx.y;
    const int tid = threadIdx.x, lane = tid & 31, wid = tid >> 5;
    const int rBeg = (wid & 3) * 2;
    const int cg   = wid >> 2;
    const float* Abase = k + (size_t)bh * S_LEN * 128 + (size_t)mt * 128 * 256;

    float acc[2][4][4];
#pragma unroll
    for (int i = 0; i < 2; i++)
#pragma unroll
        for (int t = 0; t < 4; t++)
#pragma unroll
            for (int j = 0; j < 4; j++) acc[i][t][j] = 0.f;

    ((float4*)pews)[tid] = ((const float4*)g_pew)[tid];

    // prologue: A0 (LDG/split/STS) + B0 (cp.async)
    g0_ldsts_A(sm, 0, Abase, 0, tid);
    prefB<512>(sb + G0_OFFB(0), g_w_hi, g_w_lo, 256, 0, tid);
    cpcommit();
    cpwait0(); __syncthreads();

    for (int c = 0; c < 4; ++c) {
        float4 dummy;
        (void)dummy;
        float4 rA[4];
        if (c < 3) {
#pragma unroll
            for (int t = 0; t < 4; ++t) {
                int f = tid + t * 512, row = f >> 4, fc = f & 15;
                rA[t] = *(const float4*)(Abase + (size_t)row * 256 + (c + 1) * 64 + 4 * fc);
            }
            prefB<512>(sb + G0_OFFB((c + 1) & 1), g_w_hi, g_w_lo, 256, (c + 1) * 64, tid);
            cpcommit();
        }
        const uint32_t aU = sb + (c & 1) * 32768;
        const uint32_t bU = sb + G0_OFFB(c & 1);
        mma_chunk64<2>(acc, aU, aU + 16384, bU, bU + 16384, rBeg, cg * 4, lane);
        if (c < 3) {
#pragma unroll
            for (int t = 0; t < 4; ++t) {
                int f = tid + t * 512, row = f >> 4, fc = f & 15;
                float v[4] = {rA[t].x, rA[t].y, rA[t].z, rA[t].w};
                U4b hi, lo;
#pragma unroll
                for (int j = 0; j < 4; j++) {
                    hi.b[j] = __float2bfloat16(v[j]);
                    lo.b[j] = __float2bfloat16(v[j] - __bfloat162float(hi.b[j]));
                }
                int g = fc >> 1;
                int off = ((c + 1) & 1) * 32768 + row * 128
                        + ((g ^ (row & 7)) << 4) + (fc & 1) * 8;
                *(unsigned long long*)(sm + off)         = hi.u;
                *(unsigned long long*)(sm + off + 16384) = lo.u;
            }
            cpwait0();
        }
        __syncthreads();
    }

    // epilogue: pair j feeds two act0 rows (different pe bias)
    const int r0 = lane >> 2, cof = (lane & 3) << 1;
    const size_t bhbase = (size_t)bh * NWIN;
#pragma unroll
    for (int i = 0; i < 2; i++)
#pragma unroll
        for (int t = 0; t < 4; t++) {
            int col = (cg * 4 + t) * 8 + cof;
            float* cc = acc[i][t];
#pragma unroll
            for (int h = 0; h < 2; h++) {
                int r = (rBeg + i) * 16 + r0 + (h << 3);
                int j = mt * 128 + r;
                float y0 = cc[2*h], y1 = cc[2*h + 1];
                int w1 = j >> 3, ra = j & 7;
                if (w1 < NWIN) {
                    float2 bb = *(const float2*)(pews + ra * 128 + col);
                    silu_split_store(g_a0_hi, g_a0_lo,
                        ((bhbase + w1) * 16 + ra) * 128 + col, y0 + bb.x, y1 + bb.y);
                }
                if (w1 >= 1) {
                    int rb = ra + 8;
                    float2 bb = *(const float2*)(pews + rb * 128 + col);
                    silu_split_store(g_a0_hi, g_a0_lo,
                        ((bhbase + (w1 - 1)) * 16 + rb) * 128 + col, y0 + bb.x, y1 + bb.y);
                }
            }
        }
}

// ===========================================================================
// G1..G5: 256-thread CTAs, M-tile=64, 96KB smem -> 2 CTAs/SM.
// smem: A0 @0 (hi 0/lo 8192), A1 @16384; B0 @32768 (hi/lo 16384), B1 @65536.
// Warp tile: R=1 row-tile x T=8 n-tiles (8 warps: 4 row x 2 colgroup).
// ===========================================================================
#define GS_SMEM 98304

__device__ __forceinline__ void prefA64(uint32_t bufU,
        const __nv_bfloat16* __restrict__ aHi, const __nv_bfloat16* __restrict__ aLo,
        int KD, int Mtot, int mt, int kb, int tid) {
#pragma unroll
    for (int it = 0; it < 4; ++it) {
        int i = tid + it * 256;                 // 1024 copies
        int g = i & 7, row = (i >> 3) & 63, hl = i >> 9;
        int mrow = mt * 64 + row;
        bool v = mrow < Mtot;
        const __nv_bfloat16* src = (hl ? aLo : aHi)
                                 + (size_t)(v ? mrow : 0) * KD + kb + g * 8;
        uint32_t dst = bufU + hl * 8192 + row * 128 + ((g ^ (row & 7)) << 4);
        cpasync16z(dst, src, v);
    }
}

__device__ __forceinline__ void mma_r1t8(
    float (&acc)[8][4],
    uint32_t aHiU, uint32_t aLoU, uint32_t bHiU, uint32_t bLoU,
    int rt, int cg, int lane)
{
    const int a_rowoff = (lane & 7) + (((lane >> 3) & 1) << 3);
    const int a_koff   = (lane >> 4) << 3;
    const int b_nl     = lane & 7;
    const int b_koff   = ((lane >> 3) & 1) << 3;
    const int b_nts    = lane >> 4;
#pragma unroll
    for (int kq = 0; kq < 64; kq += 16) {
        int Rr = rt * 16 + a_rowoff;
        int kc = kq + a_koff;
        int offs = Rr * 128 + (((kc >> 3) ^ (Rr & 7)) << 4);
        uint32_t aH[4], aL[4];
        ldmx4(aH, aHiU + offs);
        ldmx4(aL, aLoU + offs);
#pragma unroll
        for (int tp = 0; tp < 4; tp++) {
            int n = (cg * 8 + tp * 2 + b_nts) * 8 + b_nl;
            int cs = ((kq + b_koff) >> 3) ^ (n & 7);
            uint32_t boff = (uint32_t)(n * 128 + (cs << 4));
            uint32_t bH[4], bL[4];
            ldmx4(bH, bHiU + boff);
            ldmx4(bL, bLoU + boff);
#pragma unroll
            for (int sub = 0; sub < 2; sub++) {
                float* cc = acc[tp * 2 + sub];
                mma16816(cc, aH, bH[2*sub], bH[2*sub+1]);
                mma16816(cc, aL, bH[2*sub], bH[2*sub+1]);
                mma16816(cc, aH, bL[2*sub], bL[2*sub+1]);
            }
        }
    }
}

template<int STAGE>
__global__ void __launch_bounds__(256, 2)
gstage_kernel(float* __restrict__ gout)
{
    constexpr int KD = (STAGE == 5) ? 128 : 256;
    constexpr int NC = KD / 64;
    const __nv_bfloat16 *aHi, *aLo, *wh, *wl;
    __nv_bfloat16 *oHi = nullptr, *oLo = nullptr;
    int Mtot;
    if constexpr (STAGE == 1) { aHi=g_a0_hi; aLo=g_a0_lo; wh=g_w_hi+32768;  wl=g_w_lo+32768;  oHi=g_a1_hi; oLo=g_a1_lo; Mtot=M1; }
    if constexpr (STAGE == 2) { aHi=g_a1_hi; aLo=g_a1_lo; wh=g_w_hi+65536;  wl=g_w_lo+65536;  oHi=g_a2_hi; oLo=g_a2_lo; Mtot=M2; }
    if constexpr (STAGE == 3) { aHi=g_a2_hi; aLo=g_a2_lo; wh=g_w_hi+98304;  wl=g_w_lo+98304;  oHi=g_a3_hi; oLo=g_a3_lo; Mtot=M3; }
    if constexpr (STAGE == 4) { aHi=g_a3_hi; aLo=g_a3_lo; wh=g_w_hi+131072; wl=g_w_lo+131072; oHi=g_a4_hi; oLo=g_a4_lo; Mtot=M4; }
    if constexpr (STAGE == 5) { aHi=g_a4_hi; aLo=g_a4_lo; wh=g_w_hi+163840; wl=g_w_lo+163840; Mtot=M4; }

    extern __shared__ char sm[];
    const uint32_t sb = u32p(sm);
    const int mt = blockIdx.x;
    const int tid = threadIdx.x, lane = tid & 31, wid = tid >> 5;
    const int rt = wid & 3, cg = wid >> 2;

    float acc[8][4];
#pragma unroll
    for (int t = 0; t < 8; t++)
#pragma unroll
        for (int j = 0; j < 4; j++) acc[t][j] = 0.f;

    prefA64(sb, aHi, aLo, KD, Mtot, mt, 0, tid);
    prefB<256>(sb + 32768, wh, wl, KD, 0, tid);
    cpcommit();

    for (int c = 0; c < NC; ++c) {
        cpwait0();
        __syncthreads();
        if (c + 1 < NC) {
            int b = (c + 1) & 1;
            prefA64(sb + b * 16384, aHi, aLo, KD, Mtot, mt, (c + 1) * 64, tid);
            prefB<256>(sb + 32768 + b * 32768, wh, wl, KD, (c + 1) * 64, tid);
            cpcommit();
        }
        const uint32_t aU = sb + (c & 1) * 16384;
        const uint32_t bU = sb + 32768 + (c & 1) * 32768;
        mma_r1t8(acc, aU, aU + 8192, bU, bU + 16384, rt, cg, lane);
    }

    const int r0 = lane >> 2, cof = (lane & 3) << 1;
#pragma unroll
    for (int t = 0; t < 8; t++) {
        int col = (cg * 8 + t) * 8 + cof;
        float* cc = acc[t];
#pragma unroll
        for (int h = 0; h < 2; h++) {
            int r = rt * 16 + r0 + (h << 3);
            int m = mt * 64 + r;
            if (m < Mtot) {
                if constexpr (STAGE < 5) {
                    silu_split_store(oHi, oLo, (size_t)m * 128 + col,
                                     cc[2*h], cc[2*h + 1]);
                } else {
                    int bh = m / NWIN, w = m % NWIN;
                    *(float2*)(gout + ((size_t)bh * 512 + 1 + w) * 128 + col) =
                        make_float2(cc[2*h], cc[2*h + 1]);
                }
            }
        }
    }
}

extern "C" void kernel_launch(void* const* d_in, const int* in_sizes, int n_in,
                              void* d_out, int out_size)
{
    const float* k  = (const float*)d_in[0];
    const float* pe = (const float*)d_in[1];
    const float* wd = (const float*)d_in[2];
    const float* ws = (const float*)d_in[3];
    float* out = (float*)d_out;

    split_weights_kernel<<<(WTOT + 255) / 256, 256>>>(wd, ws);
    prep_pew_kernel<<<8, 256>>>(wd, pe);
    zero_out_kernel<<<16, 256>>>(out);

    cudaFuncSetAttribute(g0_kernel,
                         cudaFuncAttributeMaxDynamicSharedMemorySize, G0_SMEM);
    cudaFuncSetAttribute(gstage_kernel<1>,
                         cudaFuncAttributeMaxDynamicSharedMemorySize, GS_SMEM);
    cudaFuncSetAttribute(gstage_kernel<2>,
                         cudaFuncAttributeMaxDynamicSharedMemorySize, GS_SMEM);
    cudaFuncSetAttribute(gstage_kernel<3>,
                         cudaFuncAttributeMaxDynamicSharedMemorySize, GS_SMEM);
    cudaFuncSetAttribute(gstage_kernel<4>,
                         cudaFuncAttributeMaxDynamicSharedMemorySize, GS_SMEM);
    cudaFuncSetAttribute(gstage_kernel<5>,
                         cudaFuncAttributeMaxDynamicSharedMemorySize, GS_SMEM);

    g0_kernel<<<dim3(32, BH), 512, G0_SMEM>>>(k);
    gstage_kernel<1><<<(M1 + 63) / 64, 256, GS_SMEM>>>(out);   // 2044
    gstage_kernel<2><<<(M2 + 63) / 64, 256, GS_SMEM>>>(out);   // 1022
    gstage_kernel<3><<<(M3 + 63) / 64, 256, GS_SMEM>>>(out);   // 511
    gstage_kernel<4><<<(M4 + 63) / 64, 256, GS_SMEM>>>(out);   // 256
    gstage_kernel<5><<<(M4 + 63) / 64, 256, GS_SMEM>>>(out);   // 256
}